// round 3
// baseline (speedup 1.0000x reference)
#include <cuda_runtime.h>
#include <cuda_bf16.h>

// Problem dims
#define BB    32
#define SS    512
#define WIN   5
#define EMB   300
#define HH    300
#define K1    1500        // EMB*WIN
#define NOUT  128
#define MROWS (BB*SS)     // 16384

// ------------------------------------------------------------------
// Scratch (static device globals; allocation inside kernel_launch is banned)
// ------------------------------------------------------------------
__device__ float g_XE[(size_t)MROWS * K1];   // relu(embedded) [s*32+b][1500]
__device__ float g_A [(size_t)MROWS * HH];   // pre-activation (A1 then A2)
__device__ float g_H1[(size_t)MROWS * HH];   // layer1 hidden states [s*32+b][300]
__device__ float g_H2[(size_t)MROWS * HH];   // layer2 hidden states

// ------------------------------------------------------------------
// f32x2 helpers (sm_100+: packed fp32 FMA, 2x the 3-reg FFMA rate)
// ------------------------------------------------------------------
__device__ __forceinline__ void ffma2(unsigned long long &d,
                                      unsigned long long a,
                                      unsigned long long b) {
    asm("fma.rn.f32x2 %0, %1, %2, %0;" : "+l"(d) : "l"(a), "l"(b));
}
__device__ __forceinline__ unsigned long long pack2(float lo, float hi) {
    unsigned long long r;
    asm("mov.b64 %0, {%1, %2};" : "=l"(r) : "f"(lo), "f"(hi));
    return r;
}
__device__ __forceinline__ void unpack2(unsigned long long v, float &lo, float &hi) {
    asm("mov.b64 {%0, %1}, %2;" : "=f"(lo), "=f"(hi) : "l"(v));
}
__device__ __forceinline__ unsigned smem_u32(const void *p) {
    unsigned a;
    asm("{ .reg .u64 t; cvta.to.shared.u64 t, %1; cvt.u32.u64 %0, t; }"
        : "=r"(a) : "l"(p));
    return a;
}

// ------------------------------------------------------------------
// Kernel 1: embedding gather + relu.  XE[s*32+b][w*300+e] = relu(emb[x[b,s,w],e])
// ------------------------------------------------------------------
__global__ void embed_kernel(const int *__restrict__ x,
                             const float *__restrict__ emb) {
    int m = blockIdx.x;            // m = s*32 + b
    int s = m >> 5, b = m & 31;
    __shared__ int idx[WIN];
    if (threadIdx.x < WIN) idx[threadIdx.x] = x[(b * SS + s) * WIN + threadIdx.x];
    __syncthreads();
    float4 *out4 = reinterpret_cast<float4 *>(g_XE + (size_t)m * K1);
    for (int i = threadIdx.x; i < K1 / 4; i += blockDim.x) {
        int e4 = i * 4;
        int w = e4 / EMB;
        int e = e4 - w * EMB;      // EMB % 4 == 0, so a float4 never crosses segments
        float4 v = *reinterpret_cast<const float4 *>(emb + (size_t)idx[w] * EMB + e);
        v.x = fmaxf(v.x, 0.f); v.y = fmaxf(v.y, 0.f);
        v.z = fmaxf(v.z, 0.f); v.w = fmaxf(v.w, 0.f);
        out4[i] = v;
    }
}

// ------------------------------------------------------------------
// Kernel 2: tiled fp32 GEMM  C[m][n] = sum_k A[m][k]*Bw[n][k] + b1[n] (+ b2[n])
// BM=128, BN=64, BK=16, 256 threads, thread tile 4x8 via f32x2.
// PERM: store row permutation m=(s*32+b) -> out row (b*512+s)  (final projections)
// ------------------------------------------------------------------
template <bool PERM>
__global__ __launch_bounds__(256)
void gemm_nt(const float *__restrict__ A, const float *__restrict__ Bw,
             const float *__restrict__ b1, const float *__restrict__ b2,
             float *__restrict__ C, int M, int N, int K, int ldc) {
    __shared__ __align__(16) float As[16][132];
    __shared__ __align__(16) float Bs[16][68];

    const int tid = threadIdx.x;
    const int m0 = blockIdx.y * 128;
    const int n0 = blockIdx.x * 64;
    const int tx = tid & 7;     // 8 col-groups * 8 cols
    const int ty = tid >> 3;    // 32 row-groups * 4 rows

    const int a_r = tid >> 2;          // 0..63
    const int a_k = (tid & 3) * 4;     // 0,4,8,12

    unsigned long long acc[4][4];
#pragma unroll
    for (int i = 0; i < 4; i++)
#pragma unroll
        for (int j = 0; j < 4; j++) acc[i][j] = 0ULL;

    const int KT = (K + 15) >> 4;
    for (int kt = 0; kt < KT; kt++) {
        int k0 = kt * 16;
        float4 av0 = make_float4(0.f, 0.f, 0.f, 0.f);
        float4 av1 = av0, bv = av0;
        int kk = k0 + a_k;
        if (kk < K) {   // K % 4 == 0 -> full float4 in range
            av0 = *reinterpret_cast<const float4 *>(A + (size_t)(m0 + a_r) * K + kk);
            av1 = *reinterpret_cast<const float4 *>(A + (size_t)(m0 + a_r + 64) * K + kk);
            if (n0 + a_r < N)
                bv = *reinterpret_cast<const float4 *>(Bw + (size_t)(n0 + a_r) * K + kk);
        }
        __syncthreads();
        As[a_k + 0][a_r] = av0.x; As[a_k + 1][a_r] = av0.y;
        As[a_k + 2][a_r] = av0.z; As[a_k + 3][a_r] = av0.w;
        As[a_k + 0][a_r + 64] = av1.x; As[a_k + 1][a_r + 64] = av1.y;
        As[a_k + 2][a_r + 64] = av1.z; As[a_k + 3][a_r + 64] = av1.w;
        Bs[a_k + 0][a_r] = bv.x; Bs[a_k + 1][a_r] = bv.y;
        Bs[a_k + 2][a_r] = bv.z; Bs[a_k + 3][a_r] = bv.w;
        __syncthreads();

#pragma unroll
        for (int k = 0; k < 16; k++) {
            float4 a4 = *reinterpret_cast<const float4 *>(&As[k][ty * 4]);
            const ulonglong2 *bp =
                reinterpret_cast<const ulonglong2 *>(&Bs[k][tx * 8]);
            ulonglong2 bA = bp[0], bB = bp[1];
            unsigned long long a0 = pack2(a4.x, a4.x);
            unsigned long long a1 = pack2(a4.y, a4.y);
            unsigned long long a2 = pack2(a4.z, a4.z);
            unsigned long long a3 = pack2(a4.w, a4.w);
            ffma2(acc[0][0], a0, bA.x); ffma2(acc[0][1], a0, bA.y);
            ffma2(acc[0][2], a0, bB.x); ffma2(acc[0][3], a0, bB.y);
            ffma2(acc[1][0], a1, bA.x); ffma2(acc[1][1], a1, bA.y);
            ffma2(acc[1][2], a1, bB.x); ffma2(acc[1][3], a1, bB.y);
            ffma2(acc[2][0], a2, bA.x); ffma2(acc[2][1], a2, bA.y);
            ffma2(acc[2][2], a2, bB.x); ffma2(acc[2][3], a2, bB.y);
            ffma2(acc[3][0], a3, bA.x); ffma2(acc[3][1], a3, bA.y);
            ffma2(acc[3][2], a3, bB.x); ffma2(acc[3][3], a3, bB.y);
        }
    }

    // bias
    float bias[8];
#pragma unroll
    for (int jj = 0; jj < 8; jj++) {
        int n = n0 + tx * 8 + jj;
        bias[jj] = (n < N) ? (b1[n] + (b2 ? b2[n] : 0.f)) : 0.f;
    }
#pragma unroll
    for (int i = 0; i < 4; i++) {
        int m = m0 + ty * 4 + i;
        int row = PERM ? ((m & 31) * SS + (m >> 5)) : m;
        float *cp = C + (size_t)row * ldc;
#pragma unroll
        for (int j = 0; j < 4; j++) {
            int n = n0 + tx * 8 + 2 * j;
            float lo, hi;
            unpack2(acc[i][j], lo, hi);
            if (n < N)     cp[n]     = lo + bias[2 * j];
            if (n + 1 < N) cp[n + 1] = hi + bias[2 * j + 1];
        }
    }
}

// ------------------------------------------------------------------
// Kernel 3: recurrence.  One batch element per 4-CTA cluster (32 clusters).
// h_t = tanh(A[t,b,:] + W_hh @ h_{t-1}).  W slice (75 rows x 300) in registers.
// h exchanged via DSMEM (st.shared::cluster), synced with barrier.cluster.
// Thread layout (320 thr, 300 active): kc = tid/75 (k-chunk), jr = tid%75 (row).
// ------------------------------------------------------------------
__global__ void __cluster_dims__(4, 1, 1) __launch_bounds__(320)
rec_kernel(const float *__restrict__ W, const float *__restrict__ A,
           float *__restrict__ Hout) {
    __shared__ __align__(16) float hs[2][4][80];   // [buf][chunk][76 used, pad 0]
    __shared__ float ps[4][80];                    // partial sums

    const int tid  = threadIdx.x;
    const int rank = blockIdx.x & 3;
    const int b    = blockIdx.x >> 2;
    const int kc   = tid / 75;
    const int jr   = tid % 75;
    const bool active = tid < 300;

    // Load W slice into registers, pre-packed as f32x2 pairs (76th elem = 0).
    unsigned long long w2[38];
    if (active) {
        const float *wp = W + (size_t)(rank * 75 + jr) * HH + kc * 75;
#pragma unroll
        for (int i = 0; i < 37; i++) w2[i] = pack2(wp[2 * i], wp[2 * i + 1]);
        w2[37] = pack2(wp[74], 0.f);
    }
    // zero both h buffers (incl. pad element [75] which stays 0 forever)
    for (int i = tid; i < 2 * 4 * 80; i += blockDim.x)
        (&hs[0][0][0])[i] = 0.f;
    __syncthreads();
    asm volatile("barrier.cluster.arrive.aligned;" ::: "memory");
    asm volatile("barrier.cluster.wait.aligned;" ::: "memory");

    const float *arow = A + (size_t)b * HH + rank * 75;     // + t*BB*HH + jr
    float *hrow = Hout + (size_t)b * HH + rank * 75;
    int cur = 0;

    for (int t = 0; t < SS; t++) {
        float aval = 0.f;
        if (tid < 75) aval = arow[(size_t)t * BB * HH + tid];   // prefetch

        if (active) {
            const ulonglong2 *hp2 =
                reinterpret_cast<const ulonglong2 *>(&hs[cur][kc][0]);
            unsigned long long acc2 = 0ULL;
#pragma unroll
            for (int k = 0; k < 19; k++) {
                ulonglong2 hv = hp2[k];
                ffma2(acc2, w2[2 * k], hv.x);
                ffma2(acc2, w2[2 * k + 1], hv.y);
            }
            float lo, hi;
            unpack2(acc2, lo, hi);
            ps[kc][jr] = lo + hi;
        }
        __syncthreads();

        if (tid < 75) {
            float s = ps[0][tid] + ps[1][tid] + ps[2][tid] + ps[3][tid] + aval;
            float hv = tanhf(s);
            hrow[(size_t)t * BB * HH + tid] = hv;
            unsigned loc = smem_u32(&hs[cur ^ 1][rank][tid]);
#pragma unroll
            for (int r = 0; r < 4; r++) {
                unsigned rem;
                asm volatile("mapa.shared::cluster.u32 %0, %1, %2;"
                             : "=r"(rem) : "r"(loc), "r"(r));
                asm volatile("st.shared::cluster.f32 [%0], %1;"
                             :: "r"(rem), "f"(hv) : "memory");
            }
        }
        asm volatile("barrier.cluster.arrive.aligned;" ::: "memory");
        asm volatile("barrier.cluster.wait.aligned;" ::: "memory");
        cur ^= 1;
    }
}

// ------------------------------------------------------------------
// Launch sequence
// ------------------------------------------------------------------
extern "C" void kernel_launch(void *const *d_in, const int *in_sizes, int n_in,
                              void *d_out, int out_size) {
    const int   *x     = (const int *)d_in[0];
    const float *emb   = (const float *)d_in[1];
    const float *W_ih1 = (const float *)d_in[2];
    const float *W_hh1 = (const float *)d_in[3];
    const float *b_ih1 = (const float *)d_in[4];
    const float *b_hh1 = (const float *)d_in[5];
    const float *W_ih2 = (const float *)d_in[6];
    const float *W_hh2 = (const float *)d_in[7];
    const float *b_ih2 = (const float *)d_in[8];
    const float *b_hh2 = (const float *)d_in[9];
    const float *fc1_w = (const float *)d_in[10];
    const float *fc1_b = (const float *)d_in[11];
    const float *fc2_w = (const float *)d_in[12];
    const float *fc2_b = (const float *)d_in[13];
    float *out = (float *)d_out;

    float *xe, *a, *h1, *h2;
    cudaGetSymbolAddress((void **)&xe, g_XE);
    cudaGetSymbolAddress((void **)&a,  g_A);
    cudaGetSymbolAddress((void **)&h1, g_H1);
    cudaGetSymbolAddress((void **)&h2, g_H2);

    // 1) embed + relu
    embed_kernel<<<MROWS, 128>>>(x, emb);

    // 2) A1 = XE @ W_ih1^T + (b_ih1 + b_hh1)   [16384 x 1500] x [1500 x 300]
    {
        dim3 grid((HH + 63) / 64, MROWS / 128);
        gemm_nt<false><<<grid, 256>>>(xe, W_ih1, b_ih1, b_hh1, a,
                                      MROWS, HH, K1, HH);
    }
    // 3) layer-1 recurrence -> H1
    rec_kernel<<<128, 320>>>(W_hh1, a, h1);

    // 4) A2 = H1 @ W_ih2^T + (b_ih2 + b_hh2)   [16384 x 300] x [300 x 300]
    {
        dim3 grid((HH + 63) / 64, MROWS / 128);
        gemm_nt<false><<<grid, 256>>>(h1, W_ih2, b_ih2, b_hh2, a,
                                      MROWS, HH, HH, HH);
    }
    // 5) layer-2 recurrence -> H2
    rec_kernel<<<128, 320>>>(W_hh2, a, h2);

    // 6) out1 = H1 @ fc1_w^T + fc1_b ; out2 = H2 @ fc2_w^T + fc2_b
    //    (permuted store: row m = s*32+b  ->  out row b*512+s)
    {
        dim3 grid((NOUT + 63) / 64, MROWS / 128);
        gemm_nt<true><<<grid, 256>>>(h1, fc1_w, fc1_b, nullptr, out,
                                     MROWS, NOUT, HH, NOUT);
        gemm_nt<true><<<grid, 256>>>(h2, fc2_w, fc2_b, nullptr,
                                     out + (size_t)MROWS * NOUT,
                                     MROWS, NOUT, HH, NOUT);
    }
}